// round 3
// baseline (speedup 1.0000x reference)
#include <cuda_runtime.h>

// out[q] = sum_{k<=q} (Q_q.K_k)^2 V_k / (sum_{k<=q} (Q_q.K_k)^2 + EPS)
// b=2, t=2048, h=8, d=dv=64.  BM=BN=128 tiles, 512 threads, f32x2 packed FMA.

typedef unsigned long long u64;

constexpr int T_ = 2048;
constexpr int ROWSTRIDE = 512;     // h*d floats between consecutive tokens
constexpr float EPSF = 1e-5f;

// dynamic smem layout (float offsets)
constexpr int QS_OFF = 0;          // Qs[64][128]  (transposed, swizzled)
constexpr int KS_OFF = 8192;       // Ks[64][128]  (transposed, swizzled)
constexpr int VS_OFF = 16384;      // Vs[128][64]
constexpr int ST_OFF = 24576;      // St[128][128] (P transposed [k][q], swizzled)
constexpr int ZS_OFF = 40960;      // Zs[128]
constexpr size_t SMEM_BYTES = (size_t)41088 * 4;   // 164352 B

__device__ __forceinline__ u64 pk2(float x) {
    u64 r; asm("mov.b64 %0, {%1, %1};" : "=l"(r) : "f"(x)); return r;
}
__device__ __forceinline__ u64 ffma2(u64 a, u64 b, u64 c) {
    u64 d; asm("fma.rn.f32x2 %0, %1, %2, %3;" : "=l"(d) : "l"(a), "l"(b), "l"(c)); return d;
}
__device__ __forceinline__ u64 fmul2(u64 a, u64 b) {
    u64 d; asm("mul.rn.f32x2 %0, %1, %2;" : "=l"(d) : "l"(a), "l"(b)); return d;
}
__device__ __forceinline__ u64 fadd2(u64 a, u64 b) {
    u64 d; asm("add.rn.f32x2 %0, %1, %2;" : "=l"(d) : "l"(a), "l"(b)); return d;
}
__device__ __forceinline__ float2 up2(u64 a) {
    float2 f; asm("mov.b64 {%0, %1}, %2;" : "=f"(f.x), "=f"(f.y) : "l"(a)); return f;
}
__device__ __forceinline__ u64 pk(float x, float y) {
    u64 r; asm("mov.b64 %0, {%1, %2};" : "=l"(r) : "f"(x), "f"(y)); return r;
}

__global__ __launch_bounds__(512, 1)
void attn_pow2_kernel(const float* __restrict__ Qg,
                      const float* __restrict__ Kg,
                      const float* __restrict__ Vg,
                      float* __restrict__ Og)
{
    extern __shared__ float sm[];
    float* Qs = sm + QS_OFF;
    float* Ks = sm + KS_OFF;
    float* Vs = sm + VS_OFF;
    float* St = sm + ST_OFF;
    float* Zs = sm + ZS_OFF;

    const int qt  = (int)(gridDim.x - 1 - blockIdx.x);   // heavy tiles first
    const int bh  = (int)blockIdx.y;
    const int tid = (int)threadIdx.x;
    const int tx  = tid & 15;      // 16 columns of threads
    const int ty  = tid >> 4;      // 32 rows of threads
    const int q0  = ty * 4;        // 4 query rows (2 pairs)
    const int c0  = tx * 8;        // 8 key cols (GEMM1)
    const int v0  = tx * 4;        // 4 value cols (GEMM2)

    const size_t headoff = (size_t)(bh >> 3) * T_ * ROWSTRIDE + (size_t)(bh & 7) * 64;
    const int qbase = qt * 128;

    // ---- load Q tile: transpose into Qs[d][q^swz] ----
    #pragma unroll
    for (int it = 0; it < 4; it++) {
        int i  = tid + it * 512;
        int r  = i >> 4;
        int c4 = (i & 15) << 2;
        float4 v = *(const float4*)(Qg + headoff + (size_t)(qbase + r) * ROWSTRIDE + c4);
        int s  = ((c4 >> 3) & 7) << 2;
        int rs = r ^ s;
        Qs[(c4 + 0) * 128 + rs] = v.x;
        Qs[(c4 + 1) * 128 + rs] = v.y;
        Qs[(c4 + 2) * 128 + rs] = v.z;
        Qs[(c4 + 3) * 128 + rs] = v.w;
    }
    if (tid < 128) Zs[tid] = EPSF;

    u64 yacc[2][4] = {};
    u64 zacc[2]    = {};

    for (int kt = 0; kt <= qt; kt++) {
        const int kbase = kt * 128;
        __syncthreads();   // previous iteration done with Ks/Vs/St

        // ---- load K (transposed+swizzled) and V tiles ----
        #pragma unroll
        for (int it = 0; it < 4; it++) {
            int i  = tid + it * 512;
            int r  = i >> 4;
            int c4 = (i & 15) << 2;
            const float* gK = Kg + headoff + (size_t)(kbase + r) * ROWSTRIDE + c4;
            const float* gV = Vg + headoff + (size_t)(kbase + r) * ROWSTRIDE + c4;
            float4 kv = *(const float4*)gK;
            float4 vv = *(const float4*)gV;
            int s  = ((c4 >> 3) & 7) << 2;
            int rs = r ^ s;
            Ks[(c4 + 0) * 128 + rs] = kv.x;
            Ks[(c4 + 1) * 128 + rs] = kv.y;
            Ks[(c4 + 2) * 128 + rs] = kv.z;
            Ks[(c4 + 3) * 128 + rs] = kv.w;
            *(float4*)(Vs + r * 64 + c4) = vv;
        }
        __syncthreads();

        // ---- GEMM1: S[q][k] = sum_d Q[q][d]*K[k][d], pairs along q ----
        u64 sacc[2][8] = {};
        #pragma unroll 8
        for (int dd = 0; dd < 64; dd++) {
            const float* Qrow = Qs + dd * 128;
            const float* Krow = Ks + dd * 128;
            int s = ((dd >> 3) & 7) << 2;
            ulonglong2 qa = *(const ulonglong2*)(Qrow + (q0 ^ s));
            float4 k0 = *(const float4*)(Krow + (c0 ^ s));
            float4 k1 = *(const float4*)(Krow + ((c0 ^ s) ^ 4));
            u64 kd[8];
            kd[0] = pk2(k0.x); kd[1] = pk2(k0.y); kd[2] = pk2(k0.z); kd[3] = pk2(k0.w);
            kd[4] = pk2(k1.x); kd[5] = pk2(k1.y); kd[6] = pk2(k1.z); kd[7] = pk2(k1.w);
            #pragma unroll
            for (int j = 0; j < 8; j++) {
                sacc[0][j] = ffma2(qa.x, kd[j], sacc[0][j]);
                sacc[1][j] = ffma2(qa.y, kd[j], sacc[1][j]);
            }
        }

        // ---- square, causal mask (diag tile), Z rowsum, store P transposed ----
        const bool diag = (kt == qt);
        const int  sj   = (tx & 7) << 2;          // ((c0+j)>>3)&7 == tx&7 for j<8
        #pragma unroll
        for (int j = 0; j < 8; j++) {
            u64 p2[2];
            #pragma unroll
            for (int i2 = 0; i2 < 2; i2++) {
                u64 p = fmul2(sacc[i2][j], sacc[i2][j]);
                if (diag) {
                    int col  = c0 + j;
                    int row0 = q0 + 2 * i2;
                    float2 f = up2(p);
                    if (col > row0)     f.x = 0.0f;
                    if (col > row0 + 1) f.y = 0.0f;
                    p = pk(f.x, f.y);
                }
                zacc[i2] = fadd2(zacc[i2], p);
                p2[i2] = p;
            }
            float* Srow = St + (c0 + j) * 128;
            *(ulonglong2*)(Srow + (q0 ^ sj)) = make_ulonglong2(p2[0], p2[1]);
        }
        __syncthreads();

        // ---- GEMM2: Y[q][v] += sum_k P[q][k]*V[k][v], pairs along q ----
        #pragma unroll 8
        for (int kk = 0; kk < 128; kk++) {
            int s = ((kk >> 3) & 7) << 2;
            const float* Srow = St + kk * 128;
            ulonglong2 pA = *(const ulonglong2*)(Srow + (q0 ^ s));
            float4 vv = *(const float4*)(Vs + kk * 64 + v0);
            u64 vd0 = pk2(vv.x), vd1 = pk2(vv.y), vd2 = pk2(vv.z), vd3 = pk2(vv.w);
            yacc[0][0] = ffma2(pA.x, vd0, yacc[0][0]);
            yacc[0][1] = ffma2(pA.x, vd1, yacc[0][1]);
            yacc[0][2] = ffma2(pA.x, vd2, yacc[0][2]);
            yacc[0][3] = ffma2(pA.x, vd3, yacc[0][3]);
            yacc[1][0] = ffma2(pA.y, vd0, yacc[1][0]);
            yacc[1][1] = ffma2(pA.y, vd1, yacc[1][1]);
            yacc[1][2] = ffma2(pA.y, vd2, yacc[1][2]);
            yacc[1][3] = ffma2(pA.y, vd3, yacc[1][3]);
        }
    }

    // ---- reduce Z across thread columns ----
    #pragma unroll
    for (int i2 = 0; i2 < 2; i2++) {
        float2 z = up2(zacc[i2]);
        atomicAdd(&Zs[q0 + 2 * i2],     z.x);
        atomicAdd(&Zs[q0 + 2 * i2 + 1], z.y);
    }
    __syncthreads();

    // ---- write O = Y / Z ----
    #pragma unroll
    for (int i2 = 0; i2 < 2; i2++) {
        int r0 = q0 + 2 * i2;
        float ie = 1.0f / Zs[r0];
        float io = 1.0f / Zs[r0 + 1];
        float4 oe, oo;
        float2 y0 = up2(yacc[i2][0]);
        float2 y1 = up2(yacc[i2][1]);
        float2 y2 = up2(yacc[i2][2]);
        float2 y3 = up2(yacc[i2][3]);
        oe.x = y0.x * ie; oe.y = y1.x * ie; oe.z = y2.x * ie; oe.w = y3.x * ie;
        oo.x = y0.y * io; oo.y = y1.y * io; oo.z = y2.y * io; oo.w = y3.y * io;
        *(float4*)(Og + headoff + (size_t)(qbase + r0)     * ROWSTRIDE + v0) = oe;
        *(float4*)(Og + headoff + (size_t)(qbase + r0 + 1) * ROWSTRIDE + v0) = oo;
    }
}

extern "C" void kernel_launch(void* const* d_in, const int* in_sizes, int n_in,
                              void* d_out, int out_size)
{
    const float* Q = (const float*)d_in[0];
    const float* K = (const float*)d_in[1];
    const float* V = (const float*)d_in[2];
    float* O = (float*)d_out;

    cudaFuncSetAttribute(attn_pow2_kernel,
                         cudaFuncAttributeMaxDynamicSharedMemorySize,
                         (int)SMEM_BYTES);

    dim3 grid(T_ / 128, 16);
    dim3 block(512);
    attn_pow2_kernel<<<grid, block, SMEM_BYTES>>>(Q, K, V, O);
}

// round 4
// speedup vs baseline: 1.0572x; 1.0572x over previous
#include <cuda_runtime.h>

// out[q] = sum_{k<=q} (Q_q.K_k)^2 V_k / (sum_{k<=q} (Q_q.K_k)^2 + EPS)
// b=2, t=2048, h=8, d=dv=64. BM=BN=128, 256 threads, 8x8 micro-tiles,
// f32x2 packed FMA with ZERO inner-loop duplication MOVs:
//   GEMM1: pairs along k (K packed from smem), Q pre-duplicated in smem.
//   GEMM2: pairs along reduction k (P packed from St[q][k], V packed from Vt[v][k]).

typedef unsigned long long u64;

constexpr int T_ = 2048;
constexpr int RS = 512;            // h*d floats between consecutive tokens
constexpr float EPSF = 1e-5f;

// dynamic smem layout (float offsets)
constexpr int QD_OFF = 0;          // Qd[64][256]  duplicated Q, swizzled
constexpr int KS_OFF = 16384;      // Ks[64][128]  transposed, swizzled
constexpr int VT_OFF = 24576;      // Vt[64][128]  V transposed (v-major), swizzled
constexpr int ST_OFF = 32768;      // St[128][128] P row-major
constexpr int ZS_OFF = 49152;      // Zs[128]
constexpr size_t SMEM_BYTES = (size_t)49280 * 4;   // 197120 B

__device__ __forceinline__ u64 ffma2(u64 a, u64 b, u64 c) {
    u64 d; asm("fma.rn.f32x2 %0, %1, %2, %3;" : "=l"(d) : "l"(a), "l"(b), "l"(c)); return d;
}
__device__ __forceinline__ u64 fmul2(u64 a, u64 b) {
    u64 d; asm("mul.rn.f32x2 %0, %1, %2;" : "=l"(d) : "l"(a), "l"(b)); return d;
}
__device__ __forceinline__ u64 fadd2(u64 a, u64 b) {
    u64 d; asm("add.rn.f32x2 %0, %1, %2;" : "=l"(d) : "l"(a), "l"(b)); return d;
}
__device__ __forceinline__ float2 up2(u64 a) {
    float2 f; asm("mov.b64 {%0, %1}, %2;" : "=f"(f.x), "=f"(f.y) : "l"(a)); return f;
}
__device__ __forceinline__ u64 pk(float x, float y) {
    u64 r; asm("mov.b64 %0, {%1, %2};" : "=l"(r) : "f"(x), "f"(y)); return r;
}

__global__ __launch_bounds__(256, 1)
void attn_pow2_kernel(const float* __restrict__ Qg,
                      const float* __restrict__ Kg,
                      const float* __restrict__ Vg,
                      float* __restrict__ Og)
{
    extern __shared__ float sm[];
    float* Qd = sm + QD_OFF;
    float* Ks = sm + KS_OFF;
    float* Vt = sm + VT_OFF;
    float* St = sm + ST_OFF;
    float* Zs = sm + ZS_OFF;

    const int qt  = (int)(gridDim.x - 1 - blockIdx.x);   // heavy tiles first
    const int bh  = (int)blockIdx.y;
    const int tid = (int)threadIdx.x;
    const int tx  = tid & 15;      // 16 columns of threads
    const int ty  = tid >> 4;      // 16 rows of threads
    const int q0  = ty * 8;        // 8 query rows
    const int c0  = tx * 8;        // 8 key cols (GEMM1)
    const int v0  = tx * 4;        // 4 value cols (GEMM2)

    const size_t headoff = (size_t)(bh >> 3) * T_ * RS + (size_t)(bh & 7) * 64;
    const int qbase = qt * 128;

    // ---- load Q tile: duplicated transpose into Qd[d][(2q)^sw2] ----
    #pragma unroll
    for (int it = 0; it < 8; it++) {
        int i  = tid + it * 256;
        int r  = i >> 4;                 // token row 0..127
        int c4 = (i & 15) << 2;          // feature col (mult of 4)
        float4 v = *(const float4*)(Qg + headoff + (size_t)(qbase + r) * RS + c4);
        float vv[4] = {v.x, v.y, v.z, v.w};
        #pragma unroll
        for (int j = 0; j < 4; j++) {
            int dd  = c4 + j;
            int sw2 = (dd & 7) << 2;
            int idx = (2 * r) ^ sw2;
            *(float2*)(Qd + dd * 256 + idx) = make_float2(vv[j], vv[j]);
        }
    }
    if (tid < 128) Zs[tid] = EPSF;

    u64 yacc[8][4] = {};   // (even-k, odd-k) partial sums
    u64 zacc[8]    = {};

    for (int kt = 0; kt <= qt; kt++) {
        const int kbase = kt * 128;
        __syncthreads();   // prev GEMM2 done: St/Ks/Vt writable

        // ---- load K (transposed) and V (v-major transposed), both swizzled ----
        #pragma unroll
        for (int it = 0; it < 8; it++) {
            int i  = tid + it * 256;
            int r  = i >> 4;             // token 0..127
            int c4 = (i & 15) << 2;      // feature (mult of 4)
            float4 kv = *(const float4*)(Kg + headoff + (size_t)(kbase + r) * RS + c4);
            float4 vv = *(const float4*)(Vg + headoff + (size_t)(kbase + r) * RS + c4);
            int s  = ((c4 >> 3) & 7) << 2;   // same for c4..c4+3
            int rs = r ^ s;
            Ks[(c4 + 0) * 128 + rs] = kv.x;
            Ks[(c4 + 1) * 128 + rs] = kv.y;
            Ks[(c4 + 2) * 128 + rs] = kv.z;
            Ks[(c4 + 3) * 128 + rs] = kv.w;
            Vt[(c4 + 0) * 128 + rs] = vv.x;
            Vt[(c4 + 1) * 128 + rs] = vv.y;
            Vt[(c4 + 2) * 128 + rs] = vv.z;
            Vt[(c4 + 3) * 128 + rs] = vv.w;
        }
        __syncthreads();

        // ---- GEMM1: sacc[q][kpair] = sum_d Qd * Kpair (pairs along k) ----
        u64 sacc[8][4] = {};
        #pragma unroll 4
        for (int dd = 0; dd < 64; dd++) {
            const float* Qrow = Qd + dd * 256;
            const float* Krow = Ks + dd * 128;
            int s   = ((dd >> 3) & 7) << 2;
            int sw2 = (dd & 7) << 2;
            ulonglong2 kA = *(const ulonglong2*)(Krow + (c0 ^ s));        // (c0,c0+1),(c0+2,c0+3)
            ulonglong2 kB = *(const ulonglong2*)(Krow + ((c0 ^ s) ^ 4));  // (c0+4..c0+7)
            u64 kp[4] = {kA.x, kA.y, kB.x, kB.y};
            u64 qd[8];
            #pragma unroll
            for (int u = 0; u < 4; u++) {
                ulonglong2 t = *(const ulonglong2*)(Qrow + ((16 * ty + 4 * u) ^ sw2));
                qd[2 * u]     = t.x;     // dup(q0+2u)
                qd[2 * u + 1] = t.y;     // dup(q0+2u+1)
            }
            #pragma unroll
            for (int i = 0; i < 8; i++)
                #pragma unroll
                for (int p = 0; p < 4; p++)
                    sacc[i][p] = ffma2(qd[i], kp[p], sacc[i][p]);
        }

        // ---- square, causal mask (diag tile), Z rowsum, store P (row-major) ----
        const bool diag = (kt == qt);
        #pragma unroll
        for (int i = 0; i < 8; i++) {
            u64 sp[4];
            #pragma unroll
            for (int p = 0; p < 4; p++) {
                u64 pv = fmul2(sacc[i][p], sacc[i][p]);
                if (diag) {
                    int ce  = c0 + 2 * p;
                    int row = q0 + i;
                    float2 f = up2(pv);
                    if (ce > row)     f.x = 0.0f;
                    if (ce + 1 > row) f.y = 0.0f;
                    pv = pk(f.x, f.y);
                }
                sp[p] = pv;
            }
            zacc[i] = fadd2(zacc[i], fadd2(fadd2(sp[0], sp[1]), fadd2(sp[2], sp[3])));
            float* Srow = St + (q0 + i) * 128;
            *(ulonglong2*)(Srow + c0)     = make_ulonglong2(sp[0], sp[1]);
            *(ulonglong2*)(Srow + c0 + 4) = make_ulonglong2(sp[2], sp[3]);
        }
        __syncthreads();

        // ---- GEMM2: yacc[q][v] += P[q][kpair] * V[v][kpair] (pairs along k) ----
        const int sv = ((v0 >> 3) & 7) << 2;   // same for v0..v0+3
        #pragma unroll 2
        for (int kk = 0; kk < 128; kk += 4) {
            u64 vp[4][2];
            #pragma unroll
            for (int j = 0; j < 4; j++) {
                ulonglong2 t = *(const ulonglong2*)(Vt + (v0 + j) * 128 + (kk ^ sv));
                vp[j][0] = t.x;   // (V[kk],V[kk+1])
                vp[j][1] = t.y;   // (V[kk+2],V[kk+3])
            }
            #pragma unroll
            for (int i = 0; i < 8; i++) {
                ulonglong2 pq = *(const ulonglong2*)(St + (q0 + i) * 128 + kk);
                #pragma unroll
                for (int j = 0; j < 4; j++) {
                    yacc[i][j] = ffma2(pq.x, vp[j][0], yacc[i][j]);
                    yacc[i][j] = ffma2(pq.y, vp[j][1], yacc[i][j]);
                }
            }
        }
    }

    // ---- reduce Z across thread columns ----
    #pragma unroll
    for (int i = 0; i < 8; i++) {
        float2 z = up2(zacc[i]);
        atomicAdd(&Zs[q0 + i], z.x + z.y);
    }
    __syncthreads();

    // ---- write O = Y / Z (horizontal add of partial pairs) ----
    #pragma unroll
    for (int i = 0; i < 8; i++) {
        float inv = 1.0f / Zs[q0 + i];
        float2 y0 = up2(yacc[i][0]);
        float2 y1 = up2(yacc[i][1]);
        float2 y2 = up2(yacc[i][2]);
        float2 y3 = up2(yacc[i][3]);
        float4 o;
        o.x = (y0.x + y0.y) * inv;
        o.y = (y1.x + y1.y) * inv;
        o.z = (y2.x + y2.y) * inv;
        o.w = (y3.x + y3.y) * inv;
        *(float4*)(Og + headoff + (size_t)(qbase + q0 + i) * RS + v0) = o;
    }
}

extern "C" void kernel_launch(void* const* d_in, const int* in_sizes, int n_in,
                              void* d_out, int out_size)
{
    const float* Q = (const float*)d_in[0];
    const float* K = (const float*)d_in[1];
    const float* V = (const float*)d_in[2];
    float* O = (float*)d_out;

    cudaFuncSetAttribute(attn_pow2_kernel,
                         cudaFuncAttributeMaxDynamicSharedMemorySize,
                         (int)SMEM_BYTES);

    dim3 grid(T_ / 128, 16);
    dim3 block(256);
    attn_pow2_kernel<<<grid, block, SMEM_BYTES>>>(Q, K, V, O);
}

// round 5
// speedup vs baseline: 1.1584x; 1.0958x over previous
#include <cuda_runtime.h>

// out[q] = sum_{k<=q} (Q_q.K_k)^2 V_k / (sum_{k<=q} (Q_q.K_k)^2 + EPS)
// b=2, t=2048, h=8, d=dv=64.  BM=128, BN=64, 256 threads, 2 CTAs/SM,
// f32x2 packed FMA, R2 micro-kernel structure.

typedef unsigned long long u64;

constexpr int T_ = 2048;
constexpr int RS = 512;            // h*d floats between consecutive tokens
constexpr float EPSF = 1e-5f;

// dynamic smem layout (float offsets)
constexpr int QS_OFF = 0;          // Qs[64][128]  (transposed, swizzled)
constexpr int KS_OFF = 8192;       // Ks[64][64]   (transposed, swizzled)
constexpr int VS_OFF = 12288;      // Vs[64][64]
constexpr int ST_OFF = 16384;      // St[64][128]  (P transposed [k][q], swizzled)
constexpr int ZS_OFF = 24576;      // Zs[128]
constexpr size_t SMEM_BYTES = (size_t)24704 * 4;   // 98816 B -> 2 CTAs/SM

__device__ __forceinline__ u64 pk2(float x) {
    u64 r; asm("mov.b64 %0, {%1, %1};" : "=l"(r) : "f"(x)); return r;
}
__device__ __forceinline__ u64 ffma2(u64 a, u64 b, u64 c) {
    u64 d; asm("fma.rn.f32x2 %0, %1, %2, %3;" : "=l"(d) : "l"(a), "l"(b), "l"(c)); return d;
}
__device__ __forceinline__ u64 fmul2(u64 a, u64 b) {
    u64 d; asm("mul.rn.f32x2 %0, %1, %2;" : "=l"(d) : "l"(a), "l"(b)); return d;
}
__device__ __forceinline__ u64 fadd2(u64 a, u64 b) {
    u64 d; asm("add.rn.f32x2 %0, %1, %2;" : "=l"(d) : "l"(a), "l"(b)); return d;
}
__device__ __forceinline__ float2 up2(u64 a) {
    float2 f; asm("mov.b64 {%0, %1}, %2;" : "=f"(f.x), "=f"(f.y) : "l"(a)); return f;
}
__device__ __forceinline__ u64 pk(float x, float y) {
    u64 r; asm("mov.b64 %0, {%1, %2};" : "=l"(r) : "f"(x), "f"(y)); return r;
}

__global__ __launch_bounds__(256, 2)
void attn_pow2_kernel(const float* __restrict__ Qg,
                      const float* __restrict__ Kg,
                      const float* __restrict__ Vg,
                      float* __restrict__ Og)
{
    extern __shared__ float sm[];
    float* Qs = sm + QS_OFF;
    float* Ks = sm + KS_OFF;
    float* Vs = sm + VS_OFF;
    float* St = sm + ST_OFF;
    float* Zs = sm + ZS_OFF;

    const int qt  = (int)(gridDim.x - 1 - blockIdx.x);   // heavy tiles first
    const int bh  = (int)blockIdx.y;
    const int tid = (int)threadIdx.x;
    const int tx  = tid & 15;      // 16 columns of threads
    const int ty  = tid >> 4;      // 16 rows of threads
    const int q0  = ty * 8;        // 8 query rows (4 pairs)
    const int c0  = tx * 4;        // 4 key cols (GEMM1)
    const int v0  = tx * 4;        // 4 value cols (GEMM2)

    const size_t headoff = (size_t)(bh >> 3) * T_ * RS + (size_t)(bh & 7) * 64;
    const int qbase = qt * 128;

    // ---- load Q tile: transpose into Qs[d][q^swz] ----
    #pragma unroll
    for (int it = 0; it < 8; it++) {
        int i  = tid + it * 256;
        int r  = i >> 4;
        int c4 = (i & 15) << 2;
        float4 v = *(const float4*)(Qg + headoff + (size_t)(qbase + r) * RS + c4);
        int s  = ((c4 >> 3) & 7) << 2;
        int rs = r ^ s;
        Qs[(c4 + 0) * 128 + rs] = v.x;
        Qs[(c4 + 1) * 128 + rs] = v.y;
        Qs[(c4 + 2) * 128 + rs] = v.z;
        Qs[(c4 + 3) * 128 + rs] = v.w;
    }
    if (tid < 128) Zs[tid] = EPSF;

    u64 yacc[4][4] = {};
    u64 zacc[4]    = {};

    const int nkt = 2 * (qt + 1);        // number of 64-wide k tiles
    for (int kt = 0; kt < nkt; kt++) {
        const int kbase = kt * 64;
        __syncthreads();   // previous iteration done with Ks/Vs/St

        // ---- load K (transposed+swizzled) and V tiles (64 tokens) ----
        #pragma unroll
        for (int it = 0; it < 4; it++) {
            int i  = tid + it * 256;
            int r  = i >> 4;             // token 0..63
            int c4 = (i & 15) << 2;      // feature (mult of 4)
            float4 kv = *(const float4*)(Kg + headoff + (size_t)(kbase + r) * RS + c4);
            float4 vv = *(const float4*)(Vg + headoff + (size_t)(kbase + r) * RS + c4);
            int s  = ((c4 >> 3) & 7) << 2;
            int rs = r ^ s;
            Ks[(c4 + 0) * 64 + rs] = kv.x;
            Ks[(c4 + 1) * 64 + rs] = kv.y;
            Ks[(c4 + 2) * 64 + rs] = kv.z;
            Ks[(c4 + 3) * 64 + rs] = kv.w;
            *(float4*)(Vs + r * 64 + c4) = vv;
        }
        __syncthreads();

        // ---- GEMM1: S[q][k] = sum_d Q[q][d]*K[k][d], pairs along q ----
        u64 sacc[4][4] = {};
        #pragma unroll 8
        for (int dd = 0; dd < 64; dd++) {
            const float* Qrow = Qs + dd * 128;
            const float* Krow = Ks + dd * 64;
            int s = ((dd >> 3) & 7) << 2;
            ulonglong2 qa = *(const ulonglong2*)(Qrow + (q0 ^ s));
            ulonglong2 qb = *(const ulonglong2*)(Qrow + ((q0 ^ s) ^ 4));
            float4 k0 = *(const float4*)(Krow + (c0 ^ s));
            u64 kd[4];
            kd[0] = pk2(k0.x); kd[1] = pk2(k0.y); kd[2] = pk2(k0.z); kd[3] = pk2(k0.w);
            #pragma unroll
            for (int j = 0; j < 4; j++) {
                sacc[0][j] = ffma2(qa.x, kd[j], sacc[0][j]);
                sacc[1][j] = ffma2(qa.y, kd[j], sacc[1][j]);
                sacc[2][j] = ffma2(qb.x, kd[j], sacc[2][j]);
                sacc[3][j] = ffma2(qb.y, kd[j], sacc[3][j]);
            }
        }

        // ---- square, causal mask (diag tile), Z rowsum, store P transposed ----
        const bool diag = (kt == nkt - 1) || (kt == nkt - 2);
        const int  sj   = ((tx >> 1) & 7) << 2;   // ((c0+j)>>3)&7, const for j<4
        #pragma unroll
        for (int j = 0; j < 4; j++) {
            u64 p2[4];
            const int col = kbase + c0 + j - qbase;   // key pos relative to q tile
            #pragma unroll
            for (int i2 = 0; i2 < 4; i2++) {
                u64 p = fmul2(sacc[i2][j], sacc[i2][j]);
                if (diag) {
                    int row0 = q0 + 2 * i2;
                    float2 f = up2(p);
                    if (col > row0)     f.x = 0.0f;
                    if (col > row0 + 1) f.y = 0.0f;
                    p = pk(f.x, f.y);
                }
                zacc[i2] = fadd2(zacc[i2], p);
                p2[i2] = p;
            }
            float* Srow = St + (c0 + j) * 128;
            *(ulonglong2*)(Srow + (q0 ^ sj))       = make_ulonglong2(p2[0], p2[1]);
            *(ulonglong2*)(Srow + ((q0 ^ sj) ^ 4)) = make_ulonglong2(p2[2], p2[3]);
        }
        __syncthreads();

        // ---- GEMM2: Y[q][v] += sum_k P[q][k]*V[k][v], pairs along q ----
        #pragma unroll 8
        for (int kk = 0; kk < 64; kk++) {
            int s = ((kk >> 3) & 7) << 2;
            const float* Srow = St + kk * 128;
            ulonglong2 pA = *(const ulonglong2*)(Srow + (q0 ^ s));
            ulonglong2 pB = *(const ulonglong2*)(Srow + ((q0 ^ s) ^ 4));
            float4 vv = *(const float4*)(Vs + kk * 64 + v0);
            u64 vd0 = pk2(vv.x), vd1 = pk2(vv.y), vd2 = pk2(vv.z), vd3 = pk2(vv.w);
            yacc[0][0] = ffma2(pA.x, vd0, yacc[0][0]);
            yacc[0][1] = ffma2(pA.x, vd1, yacc[0][1]);
            yacc[0][2] = ffma2(pA.x, vd2, yacc[0][2]);
            yacc[0][3] = ffma2(pA.x, vd3, yacc[0][3]);
            yacc[1][0] = ffma2(pA.y, vd0, yacc[1][0]);
            yacc[1][1] = ffma2(pA.y, vd1, yacc[1][1]);
            yacc[1][2] = ffma2(pA.y, vd2, yacc[1][2]);
            yacc[1][3] = ffma2(pA.y, vd3, yacc[1][3]);
            yacc[2][0] = ffma2(pB.x, vd0, yacc[2][0]);
            yacc[2][1] = ffma2(pB.x, vd1, yacc[2][1]);
            yacc[2][2] = ffma2(pB.x, vd2, yacc[2][2]);
            yacc[2][3] = ffma2(pB.x, vd3, yacc[2][3]);
            yacc[3][0] = ffma2(pB.y, vd0, yacc[3][0]);
            yacc[3][1] = ffma2(pB.y, vd1, yacc[3][1]);
            yacc[3][2] = ffma2(pB.y, vd2, yacc[3][2]);
            yacc[3][3] = ffma2(pB.y, vd3, yacc[3][3]);
        }
    }

    // ---- reduce Z across thread columns ----
    #pragma unroll
    for (int i2 = 0; i2 < 4; i2++) {
        float2 z = up2(zacc[i2]);
        atomicAdd(&Zs[q0 + 2 * i2],     z.x);
        atomicAdd(&Zs[q0 + 2 * i2 + 1], z.y);
    }
    __syncthreads();

    // ---- write O = Y / Z ----
    #pragma unroll
    for (int i2 = 0; i2 < 4; i2++) {
        int r0 = q0 + 2 * i2;
        float ie = 1.0f / Zs[r0];
        float io = 1.0f / Zs[r0 + 1];
        float4 oe, oo;
        float2 y0 = up2(yacc[i2][0]);
        float2 y1 = up2(yacc[i2][1]);
        float2 y2 = up2(yacc[i2][2]);
        float2 y3 = up2(yacc[i2][3]);
        oe.x = y0.x * ie; oe.y = y1.x * ie; oe.z = y2.x * ie; oe.w = y3.x * ie;
        oo.x = y0.y * io; oo.y = y1.y * io; oo.z = y2.y * io; oo.w = y3.y * io;
        *(float4*)(Og + headoff + (size_t)(qbase + r0)     * RS + v0) = oe;
        *(float4*)(Og + headoff + (size_t)(qbase + r0 + 1) * RS + v0) = oo;
    }
}

extern "C" void kernel_launch(void* const* d_in, const int* in_sizes, int n_in,
                              void* d_out, int out_size)
{
    const float* Q = (const float*)d_in[0];
    const float* K = (const float*)d_in[1];
    const float* V = (const float*)d_in[2];
    float* O = (float*)d_out;

    cudaFuncSetAttribute(attn_pow2_kernel,
                         cudaFuncAttributeMaxDynamicSharedMemorySize,
                         (int)SMEM_BYTES);

    dim3 grid(T_ / 128, 16);
    dim3 block(256);
    attn_pow2_kernel<<<grid, block, SMEM_BYTES>>>(Q, K, V, O);
}

// round 7
// speedup vs baseline: 3.6410x; 3.1430x over previous
#include <cuda_runtime.h>
#include <cstdint>

typedef uint32_t u32;

constexpr int T_ = 2048;
constexpr int RS = 512;            // h*d floats between consecutive tokens
constexpr float EPSF = 1e-5f;

// smem byte offsets: bf16 tiles, 128 rows x 64 cols, padded stride 72 elems (144B)
constexpr u32 TSTRIDE = 72;
constexpr u32 TILEB   = 128 * TSTRIDE * 2;   // 18432 B
constexpr u32 QHI = 0;
constexpr u32 QLO = QHI + TILEB;
constexpr u32 KHI = QLO + TILEB;
constexpr u32 KLO = KHI + TILEB;
constexpr u32 VHI = KLO + TILEB;
constexpr u32 VLO = VHI + TILEB;
constexpr u32 SMEM_BYTES = VLO + TILEB;      // 110592 B

__device__ __forceinline__ u32 smem_u32(const void* p) {
    u32 a;
    asm("{ .reg .u64 t; cvta.to.shared.u64 t, %1; cvt.u32.u64 %0, t; }" : "=r"(a) : "l"(p));
    return a;
}
// pack2bf(x,y): low 16 = bf16(x), high 16 = bf16(y)
__device__ __forceinline__ u32 pack2bf(float x, float y) {
    u32 r; asm("cvt.rn.bf16x2.f32 %0, %1, %2;" : "=r"(r) : "f"(y), "f"(x)); return r;
}
__device__ __forceinline__ float bflo(u32 u) { return __uint_as_float(u << 16); }
__device__ __forceinline__ float bfhi(u32 u) { return __uint_as_float(u & 0xFFFF0000u); }

__device__ __forceinline__ void ldmx4(u32* r, u32 addr) {
    asm volatile("ldmatrix.sync.aligned.m8n8.x4.shared.b16 {%0,%1,%2,%3}, [%4];"
                 : "=r"(r[0]), "=r"(r[1]), "=r"(r[2]), "=r"(r[3]) : "r"(addr));
}
__device__ __forceinline__ void ldmx4t(u32* r, u32 addr) {
    asm volatile("ldmatrix.sync.aligned.m8n8.x4.trans.shared.b16 {%0,%1,%2,%3}, [%4];"
                 : "=r"(r[0]), "=r"(r[1]), "=r"(r[2]), "=r"(r[3]) : "r"(addr));
}
__device__ __forceinline__ void mma16816(float* c, const u32* a, u32 b0, u32 b1) {
    asm volatile(
        "mma.sync.aligned.m16n8k16.row.col.f32.bf16.bf16.f32 "
        "{%0,%1,%2,%3}, {%4,%5,%6,%7}, {%8,%9}, {%0,%1,%2,%3};"
        : "+f"(c[0]), "+f"(c[1]), "+f"(c[2]), "+f"(c[3])
        : "r"(a[0]), "r"(a[1]), "r"(a[2]), "r"(a[3]), "r"(b0), "r"(b1));
}

__global__ __launch_bounds__(256, 1)
void attn_pow2_mma(const float* __restrict__ Qg, const float* __restrict__ Kg,
                   const float* __restrict__ Vg, float* __restrict__ Og)
{
    extern __shared__ char smem[];
    const u32 sb = smem_u32(smem);

    const int tid  = (int)threadIdx.x;
    const int wid  = tid >> 5;
    const int lane = tid & 31;
    const int m0   = wid * 16;               // this warp's 16 query rows

    const int qt = (int)(gridDim.x - 1 - blockIdx.x);   // heavy tiles first
    const int bh = (int)blockIdx.y;
    const size_t headoff = (size_t)(bh >> 3) * T_ * RS + (size_t)(bh & 7) * 64;
    const int qbase = qt * 128;
    const int nkt = qt + 1;

    // ---- load Q tile once: bf16 hi/lo split into smem ----
    #pragma unroll
    for (int it = 0; it < 8; it++) {
        int i = tid + it * 256;
        int n = i >> 4, c4 = (i & 15) << 2;
        float4 q = *(const float4*)(Qg + headoff + (size_t)(qbase + n) * RS + c4);
        u32 h01 = pack2bf(q.x, q.y), h23 = pack2bf(q.z, q.w);
        u32 l01 = pack2bf(q.x - bflo(h01), q.y - bfhi(h01));
        u32 l23 = pack2bf(q.z - bflo(h23), q.w - bfhi(h23));
        u32 off = (u32)(n * TSTRIDE + c4) * 2;
        *(uint2*)(smem + QHI + off) = make_uint2(h01, h23);
        *(uint2*)(smem + QLO + off) = make_uint2(l01, l23);
    }

    // ldmatrix per-lane address components
    const int a_r  = m0 + (lane & 7) + ((lane >> 3) & 1) * 8;  // A (Q): rows
    const int a_c8 = (lane >> 4) * 8;                          // A: col + 8*sel
    const int bk_r  = (lane & 7) + (lane >> 4) * 8;            // B (K): n rows
    const int bk_c8 = ((lane >> 3) & 1) * 8;                   // B: d col sel
    const int vv_k  = (lane & 7) + ((lane >> 3) & 1) * 8;      // B (V, trans): k rows
    const int vv_c8 = (lane >> 4) * 8;                         // V: v col sel

    float Y[8][4];
    #pragma unroll
    for (int j = 0; j < 8; j++)
        #pragma unroll
        for (int e = 0; e < 4; e++) Y[j][e] = 0.0f;
    float z0 = 0.0f, z1 = 0.0f;
    u32 ph[8][4], pl[8][4];

    __syncthreads();

    for (int kt = 0; kt < nkt; kt++) {
        const int kbase = kt * 128;

        // ---- prefetch K,V gmem rows into registers ----
        float4 kreg[8], vreg[8];
        #pragma unroll
        for (int it = 0; it < 8; it++) {
            int i = tid + it * 256;
            int n = i >> 4, c4 = (i & 15) << 2;
            kreg[it] = *(const float4*)(Kg + headoff + (size_t)(kbase + n) * RS + c4);
            vreg[it] = *(const float4*)(Vg + headoff + (size_t)(kbase + n) * RS + c4);
        }
        __syncthreads();   // all warps done reading prev K/V tiles

        // ---- convert + store K,V bf16 hi/lo tiles ----
        #pragma unroll
        for (int it = 0; it < 8; it++) {
            int i = tid + it * 256;
            int n = i >> 4, c4 = (i & 15) << 2;
            u32 off = (u32)(n * TSTRIDE + c4) * 2;
            float4 k = kreg[it];
            u32 h01 = pack2bf(k.x, k.y), h23 = pack2bf(k.z, k.w);
            *(uint2*)(smem + KHI + off) = make_uint2(h01, h23);
            *(uint2*)(smem + KLO + off) = make_uint2(
                pack2bf(k.x - bflo(h01), k.y - bfhi(h01)),
                pack2bf(k.z - bflo(h23), k.w - bfhi(h23)));
            float4 v = vreg[it];
            u32 g01 = pack2bf(v.x, v.y), g23 = pack2bf(v.z, v.w);
            *(uint2*)(smem + VHI + off) = make_uint2(g01, g23);
            *(uint2*)(smem + VLO + off) = make_uint2(
                pack2bf(v.x - bflo(g01), v.y - bfhi(g01)),
                pack2bf(v.z - bflo(g23), v.w - bfhi(g23)));
        }
        __syncthreads();

        // ---- GEMM1: S = Qhi·Khi^T + Qhi·Klo^T + Qlo·Khi^T  (M16 x N128 x K64/warp) ----
        float S[16][4];
        #pragma unroll
        for (int j = 0; j < 16; j++)
            #pragma unroll
            for (int e = 0; e < 4; e++) S[j][e] = 0.0f;

        #pragma unroll
        for (int ks = 0; ks < 4; ks++) {
            const int d0 = ks * 16;
            u32 qoff = (u32)(a_r * TSTRIDE + d0 + a_c8) * 2;
            u32 qh4[4], ql4[4];
            ldmx4(qh4, sb + QHI + qoff);
            ldmx4(ql4, sb + QLO + qoff);
            #pragma unroll
            for (int j2 = 0; j2 < 8; j2++) {
                const int n0 = j2 * 16;
                u32 koff = (u32)((n0 + bk_r) * TSTRIDE + d0 + bk_c8) * 2;
                u32 bh4[4], bl4[4];
                ldmx4(bh4, sb + KHI + koff);
                ldmx4(bl4, sb + KLO + koff);
                mma16816(S[2 * j2],     qh4, bh4[0], bh4[1]);
                mma16816(S[2 * j2],     qh4, bl4[0], bl4[1]);
                mma16816(S[2 * j2],     ql4, bh4[0], bh4[1]);
                mma16816(S[2 * j2 + 1], qh4, bh4[2], bh4[3]);
                mma16816(S[2 * j2 + 1], qh4, bl4[2], bl4[3]);
                mma16816(S[2 * j2 + 1], ql4, bh4[2], bh4[3]);
            }
        }

        // ---- epilogue: P = S^2 (+causal mask), Z rowsum, repack as GEMM2 A-frags ----
        const bool diag = (kt == nkt - 1);
        const int rlo = m0 + (lane >> 2);
        const int rhi = rlo + 8;
        #pragma unroll
        for (int t = 0; t < 8; t++) {
            #pragma unroll
            for (int h = 0; h < 2; h++) {
                const int j = 2 * t + h;
                float p0 = S[j][0] * S[j][0];
                float p1 = S[j][1] * S[j][1];
                float p2 = S[j][2] * S[j][2];
                float p3 = S[j][3] * S[j][3];
                if (diag) {
                    int c0 = 8 * j + 2 * (lane & 3);
                    if (c0     > rlo) p0 = 0.0f;
                    if (c0 + 1 > rlo) p1 = 0.0f;
                    if (c0     > rhi) p2 = 0.0f;
                    if (c0 + 1 > rhi) p3 = 0.0f;
                }
                z0 += p0 + p1;
                z1 += p2 + p3;
                u32 H0 = pack2bf(p0, p1), H1 = pack2bf(p2, p3);
                ph[t][2 * h]     = H0;
                ph[t][2 * h + 1] = H1;
                pl[t][2 * h]     = pack2bf(p0 - bflo(H0), p1 - bfhi(H0));
                pl[t][2 * h + 1] = pack2bf(p2 - bflo(H1), p3 - bfhi(H1));
            }
        }

        // ---- GEMM2: Y += Phi·Vhi + Phi·Vlo + Plo·Vhi  (M16 x N64 x K128/warp) ----
        #pragma unroll
        for (int t = 0; t < 8; t++) {
            const int k0 = t * 16;
            #pragma unroll
            for (int v2 = 0; v2 < 4; v2++) {
                const int v0 = v2 * 16;
                u32 voff = (u32)((k0 + vv_k) * TSTRIDE + v0 + vv_c8) * 2;
                u32 vh4[4], vl4[4];
                ldmx4t(vh4, sb + VHI + voff);
                ldmx4t(vl4, sb + VLO + voff);
                mma16816(Y[2 * v2],     ph[t], vh4[0], vh4[1]);
                mma16816(Y[2 * v2],     ph[t], vl4[0], vl4[1]);
                mma16816(Y[2 * v2],     pl[t], vh4[0], vh4[1]);
                mma16816(Y[2 * v2 + 1], ph[t], vh4[2], vh4[3]);
                mma16816(Y[2 * v2 + 1], ph[t], vl4[2], vl4[3]);
                mma16816(Y[2 * v2 + 1], pl[t], vh4[2], vh4[3]);
            }
        }
    }

    // ---- finalize: reduce Z across the 4 lanes sharing each row, write O = Y/Z ----
    z0 += __shfl_xor_sync(0xffffffffu, z0, 1);
    z0 += __shfl_xor_sync(0xffffffffu, z0, 2);
    z1 += __shfl_xor_sync(0xffffffffu, z1, 1);
    z1 += __shfl_xor_sync(0xffffffffu, z1, 2);
    const float inv0 = 1.0f / (z0 + EPSF);
    const float inv1 = 1.0f / (z1 + EPSF);

    const int rlo = m0 + (lane >> 2);
    float* orow0 = Og + headoff + (size_t)(qbase + rlo)     * RS;
    float* orow1 = Og + headoff + (size_t)(qbase + rlo + 8) * RS;
    #pragma unroll
    for (int j = 0; j < 8; j++) {
        int c0 = 8 * j + 2 * (lane & 3);
        *(float2*)(orow0 + c0) = make_float2(Y[j][0] * inv0, Y[j][1] * inv0);
        *(float2*)(orow1 + c0) = make_float2(Y[j][2] * inv1, Y[j][3] * inv1);
    }
}

extern "C" void kernel_launch(void* const* d_in, const int* in_sizes, int n_in,
                              void* d_out, int out_size)
{
    const float* Q = (const float*)d_in[0];
    const float* K = (const float*)d_in[1];
    const float* V = (const float*)d_in[2];
    float* O = (float*)d_out;

    cudaFuncSetAttribute(attn_pow2_mma,
                         cudaFuncAttributeMaxDynamicSharedMemorySize,
                         (int)SMEM_BYTES);

    dim3 grid(T_ / 128, 16);
    dim3 block(256);
    attn_pow2_mma<<<grid, block, SMEM_BYTES>>>(Q, K, V, O);
}